// round 2
// baseline (speedup 1.0000x reference)
#include <cuda_runtime.h>

// Fused: k/v/q 1x1 convs (64->32 each) + sigmoid gate + conv chain 32->16->8->16.
// Layout [B,C,H,W], B=16, C=64, H=W=256. One thread = one pixel.
// Weights transposed into shared so inner loop uses broadcast LDS.128.

#define THREADS 256
#define HW 65536         // 256*256
#define NPIX (16 * HW)   // 1,048,576

__global__ __launch_bounds__(THREADS)
void fused_att_kernel(
    const float* __restrict__ kv_in,   // [16,64,256,256]
    const float* __restrict__ q_in,    // [16,64,256,256]
    const float* __restrict__ key_w,   // [32,64]
    const float* __restrict__ key_b,   // [32]
    const float* __restrict__ value_w, // [32,64]
    const float* __restrict__ value_b, // [32]
    const float* __restrict__ query_w, // [32,64]
    const float* __restrict__ query_b, // [32]
    const float* __restrict__ scale_p, // [1]
    const float* __restrict__ d1_w,    // [16,32]
    const float* __restrict__ d2_w,    // [8,16]
    const float* __restrict__ d3_w,    // [16,8]
    const float* __restrict__ d3_b,    // [16]
    float* __restrict__ out)           // [16,16,256,256]
{
    // Shared weight staging (all transposed: [in_c][out_c] so fixed-c rows are
    // contiguous -> float4 broadcast loads).
    __shared__ float sW[64][96];    // [c][ k:0..31 | v:32..63 | q:64..95 ]
    __shared__ float sD1[32][16];
    __shared__ float sD2[16][8];
    __shared__ float sD3[8][16];
    __shared__ float sBk[32], sBv[32], sBq[32], sB3[16];
    __shared__ float sScale;

    const int tid = threadIdx.x;

    for (int i = tid; i < 32 * 64; i += THREADS) {
        int o = i >> 6, c = i & 63;
        sW[c][o]      = key_w[i];
        sW[c][32 + o] = value_w[i];
        sW[c][64 + o] = query_w[i];
    }
    for (int i = tid; i < 16 * 32; i += THREADS) {
        int o = i >> 5, c = i & 31;
        sD1[c][o] = d1_w[i];
    }
    if (tid < 8 * 16)  { int o = tid >> 4, c = tid & 15; sD2[c][o] = d2_w[tid]; }
    if (tid < 16 * 8)  { int o = tid >> 3, c = tid & 7;  sD3[c][o] = d3_w[tid]; }
    if (tid < 32) {
        sBk[tid] = key_b[tid];
        sBv[tid] = value_b[tid];
        sBq[tid] = query_b[tid];
    }
    if (tid < 16) sB3[tid] = d3_b[tid];
    if (tid == 0) sScale = scale_p[0];
    __syncthreads();

    const int t = blockIdx.x * THREADS + tid;
    if (t >= NPIX) return;
    const int b = t >> 16;        // batch
    const int p = t & (HW - 1);   // spatial offset within batch

    const float* kvp = kv_in + (size_t)b * 64 * HW + p;
    const float* qp  = q_in  + (size_t)b * 64 * HW + p;

    // Accumulators: [0..31]=k, [32..63]=v, [64..95]=q
    float acc[96];
    #pragma unroll
    for (int o = 0; o < 32; ++o) {
        acc[o]      = sBk[o];
        acc[32 + o] = sBv[o];
        acc[64 + o] = sBq[o];
    }

    // ---- conv stage: 96 FMAs per channel, weights via broadcast LDS.128 ----
    #pragma unroll 2
    for (int c = 0; c < 64; ++c) {
        const float a  = kvp[(size_t)c * HW];
        const float qa = qp[(size_t)c * HW];
        const float4* wrow = reinterpret_cast<const float4*>(&sW[c][0]);
        #pragma unroll
        for (int j = 0; j < 24; ++j) {
            float4 w = wrow[j];
            float m = (j < 16) ? a : qa;   // compile-time select after unroll
            acc[4 * j + 0] = fmaf(m, w.x, acc[4 * j + 0]);
            acc[4 * j + 1] = fmaf(m, w.y, acc[4 * j + 1]);
            acc[4 * j + 2] = fmaf(m, w.z, acc[4 * j + 2]);
            acc[4 * j + 3] = fmaf(m, w.w, acc[4 * j + 3]);
        }
    }

    // ---- gate: x = sigmoid(k*q*scale) * v ----
    const float scl = sScale;
    float x[32];
    #pragma unroll
    for (int o = 0; o < 32; ++o) {
        float z = acc[o] * acc[64 + o] * scl;
        float att = 1.0f / (1.0f + __expf(-z));
        x[o] = att * acc[32 + o];
    }

    // ---- d1: 32 -> 16, relu ----
    float h1[16];
    #pragma unroll
    for (int o = 0; o < 16; ++o) h1[o] = 0.0f;
    #pragma unroll
    for (int c = 0; c < 32; ++c) {
        const float4* wrow = reinterpret_cast<const float4*>(&sD1[c][0]);
        const float xv = x[c];
        #pragma unroll
        for (int j = 0; j < 4; ++j) {
            float4 w = wrow[j];
            h1[4 * j + 0] = fmaf(xv, w.x, h1[4 * j + 0]);
            h1[4 * j + 1] = fmaf(xv, w.y, h1[4 * j + 1]);
            h1[4 * j + 2] = fmaf(xv, w.z, h1[4 * j + 2]);
            h1[4 * j + 3] = fmaf(xv, w.w, h1[4 * j + 3]);
        }
    }
    #pragma unroll
    for (int o = 0; o < 16; ++o) h1[o] = fmaxf(h1[o], 0.0f);

    // ---- d2: 16 -> 8, relu ----
    float h2[8];
    #pragma unroll
    for (int o = 0; o < 8; ++o) h2[o] = 0.0f;
    #pragma unroll
    for (int c = 0; c < 16; ++c) {
        const float4* wrow = reinterpret_cast<const float4*>(&sD2[c][0]);
        const float hv = h1[c];
        #pragma unroll
        for (int j = 0; j < 2; ++j) {
            float4 w = wrow[j];
            h2[4 * j + 0] = fmaf(hv, w.x, h2[4 * j + 0]);
            h2[4 * j + 1] = fmaf(hv, w.y, h2[4 * j + 1]);
            h2[4 * j + 2] = fmaf(hv, w.z, h2[4 * j + 2]);
            h2[4 * j + 3] = fmaf(hv, w.w, h2[4 * j + 3]);
        }
    }
    #pragma unroll
    for (int o = 0; o < 8; ++o) h2[o] = fmaxf(h2[o], 0.0f);

    // ---- d3: 8 -> 16, + bias ----
    float o16[16];
    #pragma unroll
    for (int o = 0; o < 16; ++o) o16[o] = sB3[o];
    #pragma unroll
    for (int c = 0; c < 8; ++c) {
        const float4* wrow = reinterpret_cast<const float4*>(&sD3[c][0]);
        const float hv = h2[c];
        #pragma unroll
        for (int j = 0; j < 4; ++j) {
            float4 w = wrow[j];
            o16[4 * j + 0] = fmaf(hv, w.x, o16[4 * j + 0]);
            o16[4 * j + 1] = fmaf(hv, w.y, o16[4 * j + 1]);
            o16[4 * j + 2] = fmaf(hv, w.z, o16[4 * j + 2]);
            o16[4 * j + 3] = fmaf(hv, w.w, o16[4 * j + 3]);
        }
    }

    // ---- store: out[b][o][p] ----
    float* op = out + ((size_t)b * 16) * HW + p;
    #pragma unroll
    for (int o = 0; o < 16; ++o)
        op[(size_t)o * HW] = o16[o];
}

extern "C" void kernel_launch(void* const* d_in, const int* in_sizes, int n_in,
                              void* d_out, int out_size)
{
    const float* kv_in   = (const float*)d_in[0];
    const float* q_in    = (const float*)d_in[1];
    const float* key_w   = (const float*)d_in[2];
    const float* key_b   = (const float*)d_in[3];
    const float* value_w = (const float*)d_in[4];
    const float* value_b = (const float*)d_in[5];
    const float* query_w = (const float*)d_in[6];
    const float* query_b = (const float*)d_in[7];
    const float* scale_p = (const float*)d_in[8];
    const float* d1_w    = (const float*)d_in[9];
    const float* d2_w    = (const float*)d_in[10];
    const float* d3_w    = (const float*)d_in[11];
    const float* d3_b    = (const float*)d_in[12];
    float* out = (float*)d_out;

    dim3 grid(NPIX / THREADS);
    dim3 block(THREADS);
    fused_att_kernel<<<grid, block>>>(
        kv_in, q_in, key_w, key_b, value_w, value_b, query_w, query_b,
        scale_p, d1_w, d2_w, d3_w, d3_b, out);
}

// round 3
// speedup vs baseline: 1.1244x; 1.1244x over previous
#include <cuda_runtime.h>

// Fused: k/v/q 1x1 convs (64->32) + sigmoid gate + conv chain 32->16->8->16.
// f32x2 packed FMAs across output-channel pairs (FFMA2 via PTX fma.rn.f32x2).
// One thread = one pixel. Weights transposed in shared, read as ulonglong2.

#define THREADS 256
#define HW 65536
#define NPIX (16 * HW)

typedef unsigned long long u64;

__device__ __forceinline__ u64 ffma2(u64 a, u64 b, u64 c) {
    u64 d;
    asm("fma.rn.f32x2 %0, %1, %2, %3;" : "=l"(d) : "l"(a), "l"(b), "l"(c));
    return d;
}
__device__ __forceinline__ u64 fmul2(u64 a, u64 b) {
    u64 d;
    asm("mul.rn.f32x2 %0, %1, %2;" : "=l"(d) : "l"(a), "l"(b));
    return d;
}
__device__ __forceinline__ u64 pack2(float lo, float hi) {
    u64 d;
    asm("mov.b64 %0, {%1, %2};" : "=l"(d) : "f"(lo), "f"(hi));
    return d;
}
__device__ __forceinline__ void unpack2(u64 v, float& lo, float& hi) {
    asm("mov.b64 {%0, %1}, %2;" : "=f"(lo), "=f"(hi) : "l"(v));
}

__global__ __launch_bounds__(THREADS, 2)
void fused_att_kernel(
    const float* __restrict__ kv_in, const float* __restrict__ q_in,
    const float* __restrict__ key_w, const float* __restrict__ key_b,
    const float* __restrict__ value_w, const float* __restrict__ value_b,
    const float* __restrict__ query_w, const float* __restrict__ query_b,
    const float* __restrict__ scale_p,
    const float* __restrict__ d1_w, const float* __restrict__ d2_w,
    const float* __restrict__ d3_w, const float* __restrict__ d3_b,
    float* __restrict__ out)
{
    // [c][ k:0..31 | v:32..63 | q:64..95 ] ; rows 384B (16B-aligned)
    __shared__ __align__(16) float sW[64][96];
    __shared__ __align__(16) float sD1[32][16];
    __shared__ __align__(16) float sD2[16][8];
    __shared__ __align__(16) float sD3[8][16];
    __shared__ __align__(16) float sBk[32], sBv[32], sBq[32], sB3[16];
    __shared__ float sScale;

    const int tid = threadIdx.x;

    for (int i = tid; i < 32 * 64; i += THREADS) {
        int o = i >> 6, c = i & 63;
        sW[c][o]      = key_w[i];
        sW[c][32 + o] = value_w[i];
        sW[c][64 + o] = query_w[i];
    }
    for (int i = tid; i < 16 * 32; i += THREADS) {
        int o = i >> 5, c = i & 31;
        sD1[c][o] = d1_w[i];
    }
    if (tid < 8 * 16) { int o = tid >> 4, c = tid & 15; sD2[c][o] = d2_w[tid]; }
    if (tid < 16 * 8) { int o = tid >> 3, c = tid & 7;  sD3[c][o] = d3_w[tid]; }
    if (tid < 32) { sBk[tid] = key_b[tid]; sBv[tid] = value_b[tid]; sBq[tid] = query_b[tid]; }
    if (tid < 16) sB3[tid] = d3_b[tid];
    if (tid == 0) sScale = scale_p[0];
    __syncthreads();

    const int t = blockIdx.x * THREADS + tid;
    const int b = t >> 16;
    const int p = t & (HW - 1);

    const float* kvp = kv_in + (size_t)b * 64 * HW + p;
    const float* qp  = q_in  + (size_t)b * 64 * HW + p;

    // Packed accumulators: 16 x f32x2 each for k, v, q  (96 regs total)
    u64 accK[16], accV[16], accQ[16];
    {
        const u64* bk = reinterpret_cast<const u64*>(sBk);
        const u64* bv = reinterpret_cast<const u64*>(sBv);
        const u64* bq = reinterpret_cast<const u64*>(sBq);
        #pragma unroll
        for (int j = 0; j < 16; ++j) { accK[j] = bk[j]; accV[j] = bv[j]; accQ[j] = bq[j]; }
    }

    // ---- conv stage: 48 FFMA2 per channel ----
    #pragma unroll 2
    for (int c = 0; c < 64; ++c) {
        const float a  = __ldg(kvp + (size_t)c * HW);
        const float qa = __ldg(qp  + (size_t)c * HW);
        const u64 aa = pack2(a, a);
        const u64 qq = pack2(qa, qa);
        const ulonglong2* wrow = reinterpret_cast<const ulonglong2*>(&sW[c][0]);
        #pragma unroll
        for (int j = 0; j < 8; ++j) {
            ulonglong2 w = wrow[j];            // k pairs 2j, 2j+1
            accK[2 * j]     = ffma2(aa, w.x, accK[2 * j]);
            accK[2 * j + 1] = ffma2(aa, w.y, accK[2 * j + 1]);
        }
        #pragma unroll
        for (int j = 0; j < 8; ++j) {
            ulonglong2 w = wrow[8 + j];        // v pairs
            accV[2 * j]     = ffma2(aa, w.x, accV[2 * j]);
            accV[2 * j + 1] = ffma2(aa, w.y, accV[2 * j + 1]);
        }
        #pragma unroll
        for (int j = 0; j < 8; ++j) {
            ulonglong2 w = wrow[16 + j];       // q pairs
            accQ[2 * j]     = ffma2(qq, w.x, accQ[2 * j]);
            accQ[2 * j + 1] = ffma2(qq, w.y, accQ[2 * j + 1]);
        }
    }

    // ---- gate: x = sigmoid(k*q*scale) * v ---- (reuse accV as x storage)
    const float scl = sScale;
    const u64 scl2 = pack2(scl, scl);
    float x[32];
    #pragma unroll
    for (int j = 0; j < 16; ++j) {
        u64 z2 = fmul2(fmul2(accK[j], accQ[j]), scl2);
        float z0, z1;
        unpack2(z2, z0, z1);
        float a0 = __fdividef(1.0f, 1.0f + __expf(-z0));
        float a1 = __fdividef(1.0f, 1.0f + __expf(-z1));
        u64 x2 = fmul2(pack2(a0, a1), accV[j]);
        unpack2(x2, x[2 * j], x[2 * j + 1]);
    }

    // ---- d1: 32 -> 16, relu ----
    u64 h1p[8];
    #pragma unroll
    for (int j = 0; j < 8; ++j) h1p[j] = 0ull;
    #pragma unroll
    for (int c = 0; c < 32; ++c) {
        const u64 xx = pack2(x[c], x[c]);
        const ulonglong2* wrow = reinterpret_cast<const ulonglong2*>(&sD1[c][0]);
        #pragma unroll
        for (int j = 0; j < 4; ++j) {
            ulonglong2 w = wrow[j];
            h1p[2 * j]     = ffma2(xx, w.x, h1p[2 * j]);
            h1p[2 * j + 1] = ffma2(xx, w.y, h1p[2 * j + 1]);
        }
    }
    float h1[16];
    #pragma unroll
    for (int j = 0; j < 8; ++j) {
        float lo, hi; unpack2(h1p[j], lo, hi);
        h1[2 * j]     = fmaxf(lo, 0.0f);
        h1[2 * j + 1] = fmaxf(hi, 0.0f);
    }

    // ---- d2: 16 -> 8, relu ----
    u64 h2p[4];
    #pragma unroll
    for (int j = 0; j < 4; ++j) h2p[j] = 0ull;
    #pragma unroll
    for (int c = 0; c < 16; ++c) {
        const u64 hh = pack2(h1[c], h1[c]);
        const ulonglong2* wrow = reinterpret_cast<const ulonglong2*>(&sD2[c][0]);
        #pragma unroll
        for (int j = 0; j < 2; ++j) {
            ulonglong2 w = wrow[j];
            h2p[2 * j]     = ffma2(hh, w.x, h2p[2 * j]);
            h2p[2 * j + 1] = ffma2(hh, w.y, h2p[2 * j + 1]);
        }
    }
    float h2[8];
    #pragma unroll
    for (int j = 0; j < 4; ++j) {
        float lo, hi; unpack2(h2p[j], lo, hi);
        h2[2 * j]     = fmaxf(lo, 0.0f);
        h2[2 * j + 1] = fmaxf(hi, 0.0f);
    }

    // ---- d3: 8 -> 16, + bias ----
    u64 o16p[8];
    {
        const u64* b3 = reinterpret_cast<const u64*>(sB3);
        #pragma unroll
        for (int j = 0; j < 8; ++j) o16p[j] = b3[j];
    }
    #pragma unroll
    for (int c = 0; c < 8; ++c) {
        const u64 hh = pack2(h2[c], h2[c]);
        const ulonglong2* wrow = reinterpret_cast<const ulonglong2*>(&sD3[c][0]);
        #pragma unroll
        for (int j = 0; j < 4; ++j) {
            ulonglong2 w = wrow[j];
            o16p[2 * j]     = ffma2(hh, w.x, o16p[2 * j]);
            o16p[2 * j + 1] = ffma2(hh, w.y, o16p[2 * j + 1]);
        }
    }

    // ---- store ----
    float* op = out + ((size_t)b * 16) * HW + p;
    #pragma unroll
    for (int j = 0; j < 8; ++j) {
        float lo, hi; unpack2(o16p[j], lo, hi);
        op[(size_t)(2 * j) * HW]     = lo;
        op[(size_t)(2 * j + 1) * HW] = hi;
    }
}

extern "C" void kernel_launch(void* const* d_in, const int* in_sizes, int n_in,
                              void* d_out, int out_size)
{
    const float* kv_in   = (const float*)d_in[0];
    const float* q_in    = (const float*)d_in[1];
    const float* key_w   = (const float*)d_in[2];
    const float* key_b   = (const float*)d_in[3];
    const float* value_w = (const float*)d_in[4];
    const float* value_b = (const float*)d_in[5];
    const float* query_w = (const float*)d_in[6];
    const float* query_b = (const float*)d_in[7];
    const float* scale_p = (const float*)d_in[8];
    const float* d1_w    = (const float*)d_in[9];
    const float* d2_w    = (const float*)d_in[10];
    const float* d3_w    = (const float*)d_in[11];
    const float* d3_b    = (const float*)d_in[12];
    float* out = (float*)d_out;

    fused_att_kernel<<<NPIX / THREADS, THREADS>>>(
        kv_in, q_in, key_w, key_b, value_w, value_b, query_w, query_b,
        scale_p, d1_w, d2_w, d3_w, d3_b, out);
}

// round 5
// speedup vs baseline: 1.9220x; 1.7093x over previous
#include <cuda_runtime.h>
#include <cstdint>

#define HW      65536
#define NPIX    (16 * HW)
#define TPB     384
#define TILE_PX 128
#define NBLK    (NPIX / TILE_PX)   // 8192

typedef unsigned long long u64;

__device__ __forceinline__ u64 ffma2(u64 a, u64 b, u64 c) {
    u64 d;
    asm("fma.rn.f32x2 %0, %1, %2, %3;" : "=l"(d) : "l"(a), "l"(b), "l"(c));
    return d;
}
__device__ __forceinline__ u64 pack2(float lo, float hi) {
    u64 d;
    asm("mov.b64 %0, {%1, %2};" : "=l"(d) : "f"(lo), "f"(hi));
    return d;
}
__device__ __forceinline__ void unpack2(u64 v, float& lo, float& hi) {
    asm("mov.b64 {%0, %1}, %2;" : "=f"(lo), "=f"(hi) : "l"(v));
}

// ---- dynamic smem layout (float indices) ----
#define F_SW    0                      // [64][96]           6144 floats
#define F_SOUT  6144                   // [96][128]          12288 floats
#define F_SD1   (F_SOUT + 12288)       // [32][16]           512
#define F_SD2   (F_SD1 + 512)          // [16][8]            128
#define F_SD3   (F_SD2 + 128)          // [8][16]            128
#define F_SBIAS (F_SD3 + 128)          // [96] (k|v|q biases)
#define F_SB3   (F_SBIAS + 96)         // [16]
#define F_SSCL  (F_SB3 + 16)           // [1]
#define F_TOTAL (F_SSCL + 16)
#define SMEM_BYTES (F_TOTAL * 4)       // ~77.5 KB

__global__ void __launch_bounds__(TPB, 2)
fused_tiled_kernel(
    const float* __restrict__ kv_in, const float* __restrict__ q_in,
    const float* __restrict__ key_w, const float* __restrict__ key_b,
    const float* __restrict__ value_w, const float* __restrict__ value_b,
    const float* __restrict__ query_w, const float* __restrict__ query_b,
    const float* __restrict__ scale_p,
    const float* __restrict__ d1_w, const float* __restrict__ d2_w,
    const float* __restrict__ d3_w, const float* __restrict__ d3_b,
    float* __restrict__ out)
{
    extern __shared__ __align__(16) float sm[];
    float* sW    = sm + F_SW;     // [c][96]
    float* sOut  = sm + F_SOUT;   // [out][128]
    float* sD1   = sm + F_SD1;    // [c][16]
    float* sD2   = sm + F_SD2;    // [c][8]
    float* sD3   = sm + F_SD3;    // [c][16]
    float* sBias = sm + F_SBIAS;
    float* sB3   = sm + F_SB3;
    float* sScl  = sm + F_SSCL;

    const int tid  = threadIdx.x;
    const int wid  = tid >> 5;       // 0..11: out-group (8 outs each)
    const int lane = tid & 31;       // px-group (4 px each)

    // ---- stage weights (transposed: sW[c][o]) + biases + chain ----
    for (int i = tid; i < 96 * 64; i += TPB) {
        int o = i >> 6, c = i & 63;
        float w = (o < 32) ? key_w[o * 64 + c]
                : (o < 64) ? value_w[(o - 32) * 64 + c]
                           : query_w[(o - 64) * 64 + c];
        sW[c * 96 + o] = w;
    }
    for (int i = tid; i < 16 * 32; i += TPB) {   // sD1[c][o] = d1_w[o][c]
        int o = i >> 5, c = i & 31;
        sD1[c * 16 + o] = d1_w[i];
    }
    if (tid < 128) { int o = tid >> 4, c = tid & 15; sD2[c * 8 + o]  = d2_w[tid]; }
    if (tid < 128) { int o = tid >> 3, c = tid & 7;  sD3[c * 16 + o] = d3_w[tid]; }
    if (tid < 32) {
        sBias[tid]      = key_b[tid];
        sBias[32 + tid] = value_b[tid];
        sBias[64 + tid] = query_b[tid];
    }
    if (tid < 16) sB3[tid] = d3_b[tid];
    if (tid == 0) sScl[0] = scale_p[0];
    __syncthreads();

    // ---- conv stage ----
    const int p0   = blockIdx.x * TILE_PX;
    const int b    = p0 >> 16;
    const int poff = p0 & (HW - 1);
    const int px0  = lane * 4;

    const float* src = ((wid < 8) ? kv_in : q_in)
                     + (size_t)b * 64 * HW + poff + px0;

    // acc[px][j] = outputs (8*wid + 2j, 8*wid + 2j + 1) for pixel px0+px
    u64 acc[4][4];
    {
        const u64* bp = reinterpret_cast<const u64*>(sBias) + wid * 4;
        u64 b0 = bp[0], b1 = bp[1], b2 = bp[2], b3 = bp[3];
        #pragma unroll
        for (int px = 0; px < 4; ++px) {
            acc[px][0] = b0; acc[px][1] = b1; acc[px][2] = b2; acc[px][3] = b3;
        }
    }

    #pragma unroll 4
    for (int c = 0; c < 64; ++c) {
        float4 a = *reinterpret_cast<const float4*>(src + (size_t)c * HW);
        const u64* wp = reinterpret_cast<const u64*>(&sW[c * 96 + wid * 8]);
        u64 w0 = wp[0], w1 = wp[1], w2 = wp[2], w3 = wp[3];
        u64 a0 = pack2(a.x, a.x);
        u64 a1 = pack2(a.y, a.y);
        u64 a2 = pack2(a.z, a.z);
        u64 a3 = pack2(a.w, a.w);
        acc[0][0] = ffma2(a0, w0, acc[0][0]);
        acc[0][1] = ffma2(a0, w1, acc[0][1]);
        acc[0][2] = ffma2(a0, w2, acc[0][2]);
        acc[0][3] = ffma2(a0, w3, acc[0][3]);
        acc[1][0] = ffma2(a1, w0, acc[1][0]);
        acc[1][1] = ffma2(a1, w1, acc[1][1]);
        acc[1][2] = ffma2(a1, w2, acc[1][2]);
        acc[1][3] = ffma2(a1, w3, acc[1][3]);
        acc[2][0] = ffma2(a2, w0, acc[2][0]);
        acc[2][1] = ffma2(a2, w1, acc[2][1]);
        acc[2][2] = ffma2(a2, w2, acc[2][2]);
        acc[2][3] = ffma2(a2, w3, acc[2][3]);
        acc[3][0] = ffma2(a3, w0, acc[3][0]);
        acc[3][1] = ffma2(a3, w1, acc[3][1]);
        acc[3][2] = ffma2(a3, w2, acc[3][2]);
        acc[3][3] = ffma2(a3, w3, acc[3][3]);
    }

    // ---- redistribute conv outputs via smem: sOut[out][px] ----
    #pragma unroll
    for (int j = 0; j < 4; ++j) {
        float l0, h0, l1, h1, l2, h2, l3, h3;
        unpack2(acc[0][j], l0, h0);
        unpack2(acc[1][j], l1, h1);
        unpack2(acc[2][j], l2, h2);
        unpack2(acc[3][j], l3, h3);
        float4 lo4 = make_float4(l0, l1, l2, l3);
        float4 hi4 = make_float4(h0, h1, h2, h3);
        int o0 = 8 * wid + 2 * j;
        *reinterpret_cast<float4*>(&sOut[o0 * TILE_PX + px0])       = lo4;
        *reinterpret_cast<float4*>(&sOut[(o0 + 1) * TILE_PX + px0]) = hi4;
    }
    __syncthreads();

    // ---- epilogue: threads 0..127 each take one pixel ----
    if (tid < TILE_PX) {
        const int px = tid;
        const float scl = sScl[0];

        float x[32];
        #pragma unroll
        for (int o = 0; o < 32; ++o) {
            float kk = sOut[o * TILE_PX + px];          // bias already in acc
            float vv = sOut[(32 + o) * TILE_PX + px];
            float qq = sOut[(64 + o) * TILE_PX + px];
            float z = kk * qq * scl;
            float g = __fdividef(1.0f, 1.0f + __expf(-z));
            x[o] = g * vv;
        }

        float h1[16];
        #pragma unroll
        for (int o = 0; o < 16; ++o) h1[o] = 0.0f;
        #pragma unroll
        for (int c = 0; c < 32; ++c) {
            const float4* wr = reinterpret_cast<const float4*>(&sD1[c * 16]);
            float xv = x[c];
            #pragma unroll
            for (int j = 0; j < 4; ++j) {
                float4 w = wr[j];
                h1[4*j+0] = fmaf(xv, w.x, h1[4*j+0]);
                h1[4*j+1] = fmaf(xv, w.y, h1[4*j+1]);
                h1[4*j+2] = fmaf(xv, w.z, h1[4*j+2]);
                h1[4*j+3] = fmaf(xv, w.w, h1[4*j+3]);
            }
        }
        #pragma unroll
        for (int o = 0; o < 16; ++o) h1[o] = fmaxf(h1[o], 0.0f);

        float h2[8];
        #pragma unroll
        for (int o = 0; o < 8; ++o) h2[o] = 0.0f;
        #pragma unroll
        for (int c = 0; c < 16; ++c) {
            const float4* wr = reinterpret_cast<const float4*>(&sD2[c * 8]);
            float hv = h1[c];
            #pragma unroll
            for (int j = 0; j < 2; ++j) {
                float4 w = wr[j];
                h2[4*j+0] = fmaf(hv, w.x, h2[4*j+0]);
                h2[4*j+1] = fmaf(hv, w.y, h2[4*j+1]);
                h2[4*j+2] = fmaf(hv, w.z, h2[4*j+2]);
                h2[4*j+3] = fmaf(hv, w.w, h2[4*j+3]);
            }
        }
        #pragma unroll
        for (int o = 0; o < 8; ++o) h2[o] = fmaxf(h2[o], 0.0f);

        float o16[16];
        #pragma unroll
        for (int o = 0; o < 16; ++o) o16[o] = sB3[o];
        #pragma unroll
        for (int c = 0; c < 8; ++c) {
            const float4* wr = reinterpret_cast<const float4*>(&sD3[c * 16]);
            float hv = h2[c];
            #pragma unroll
            for (int j = 0; j < 4; ++j) {
                float4 w = wr[j];
                o16[4*j+0] = fmaf(hv, w.x, o16[4*j+0]);
                o16[4*j+1] = fmaf(hv, w.y, o16[4*j+1]);
                o16[4*j+2] = fmaf(hv, w.z, o16[4*j+2]);
                o16[4*j+3] = fmaf(hv, w.w, o16[4*j+3]);
            }
        }

        float* op = out + ((size_t)b * 16) * HW + poff + px;
        #pragma unroll
        for (int o = 0; o < 16; ++o)
            op[(size_t)o * HW] = o16[o];
    }
}

extern "C" void kernel_launch(void* const* d_in, const int* in_sizes, int n_in,
                              void* d_out, int out_size)
{
    cudaFuncSetAttribute(fused_tiled_kernel,
                         cudaFuncAttributeMaxDynamicSharedMemorySize, SMEM_BYTES);
    fused_tiled_kernel<<<NBLK, TPB, SMEM_BYTES>>>(
        (const float*)d_in[0], (const float*)d_in[1],
        (const float*)d_in[2], (const float*)d_in[3],
        (const float*)d_in[4], (const float*)d_in[5],
        (const float*)d_in[6], (const float*)d_in[7],
        (const float*)d_in[8],
        (const float*)d_in[9], (const float*)d_in[10],
        (const float*)d_in[11], (const float*)d_in[12],
        (float*)d_out);
}